// round 10
// baseline (speedup 1.0000x reference)
#include <cuda_runtime.h>
#include <cuda_bf16.h>
#include <stdint.h>

// Equivariant linear via block-diagonal GEMMs, bf16 3-term emulation on
// m16n8k16 tensor cores.
//  - W: pre-split bf16 (hi,lo) globals -> smem via cp.async, 2-stage pipeline.
//  - x: LDG f32 into registers one chunk ahead; split hi/lo ONCE per CTA into
//       bf16 smem (single buffer, between syncs); B fragments via ldmatrix.
// acc += wh*xh + wl*xh + wh*xl   (dropped wl*xl ~ 2^-18).
// Blocks (mul, d, x_off, w_off):
//   (256,1,0,0) (128,3,256,65536) (64,5,640,81920) (32,7,960,86016)

#define FEAT 1184
#define BATCH_N 131072
#define NT 256
#define W_DIM 87040

__device__ __nv_bfloat16 g_wh[W_DIM];
__device__ __nv_bfloat16 g_wl[W_DIM];

__device__ __forceinline__ void cp16(uint32_t saddr, const void* gaddr) {
    asm volatile("cp.async.ca.shared.global [%0], [%1], 16;" :: "r"(saddr), "l"(gaddr));
}
__device__ __forceinline__ void ldsm4(unsigned* r, uint32_t a) {
    asm volatile("ldmatrix.sync.aligned.m8n8.x4.shared.b16 {%0,%1,%2,%3}, [%4];"
        : "=r"(r[0]), "=r"(r[1]), "=r"(r[2]), "=r"(r[3]) : "r"(a));
}
__device__ __forceinline__ void ldsm2(unsigned* r, uint32_t a) {
    asm volatile("ldmatrix.sync.aligned.m8n8.x2.shared.b16 {%0,%1}, [%2];"
        : "=r"(r[0]), "=r"(r[1]) : "r"(a));
}
__device__ __forceinline__ void ldsm2t(unsigned* r, uint32_t a) {
    asm volatile("ldmatrix.sync.aligned.m8n8.x2.trans.shared.b16 {%0,%1}, [%2];"
        : "=r"(r[0]), "=r"(r[1]) : "r"(a));
}
__device__ __forceinline__ void mma16(float* d, const unsigned* a, const unsigned* b) {
    asm volatile("mma.sync.aligned.m16n8k16.row.col.f32.bf16.bf16.f32 "
        "{%0,%1,%2,%3}, {%4,%5,%6,%7}, {%8,%9}, {%0,%1,%2,%3};"
        : "+f"(d[0]), "+f"(d[1]), "+f"(d[2]), "+f"(d[3])
        : "r"(a[0]), "r"(a[1]), "r"(a[2]), "r"(a[3]), "r"(b[0]), "r"(b[1]));
}
__device__ __forceinline__ unsigned cvt2(float vh, float vl) {
    unsigned r;
    asm("cvt.rn.bf16x2.f32 %0, %1, %2;" : "=r"(r) : "f"(vh), "f"(vl));
    return r;
}
// split two floats -> packed hi word {v1,v0} and residual word
__device__ __forceinline__ void split2(float v0, float v1, unsigned &wh, unsigned &wl) {
    wh = cvt2(v1, v0);
    float h0 = __uint_as_float(wh << 16);
    float h1 = __uint_as_float(wh & 0xffff0000u);
    wl = cvt2(v1 - h1, v0 - h0);
}

__global__ void wsplit_kernel(const float* __restrict__ w) {
    int idx = blockIdx.x * NT + threadIdx.x;
    if (idx >= W_DIM) return;
    float c = (idx < 65536) ? 0.0625f
            : (idx < 81920) ? 0.08838834764831845f
            : (idx < 86016) ? 0.125f
                            : 0.17677669529663687f;
    float v = w[idx] * c;
    __nv_bfloat16 h = __float2bfloat16_rn(v);
    g_wh[idx] = h;
    g_wl[idx] = __float2bfloat16_rn(v - __bfloat162float(h));
}

__host__ __device__ constexpr int cmax(int a, int b) { return a > b ? a : b; }
__host__ __device__ constexpr int csmb(int D, int MCTA, int NB, int KC) {
    int KSh = KC + 8, NCOL = NB * D, NS = NCOL + 8;
    int SWB = 2 * MCTA * KSh * 2;                 // per W stage (hi+lo), bytes
    int XW  = (D == 1) ? NB * KSh : KC * NS;      // halves per x array
    int mainb = 2 * SWB + 2 * XW * 2;
    int epib  = (D == 1) ? 0 : MCTA * (NCOL + 2) * 4;
    return cmax(mainb, epib);
}

template<int MUL, int D, int XO, int WO, int MCTA, int NB, int KC, int WM, int WN,
         int MINB>
__global__ __launch_bounds__(NT, MINB)
void eqlin3(const float* __restrict__ x, float* __restrict__ y)
{
    constexpr int NCOL = NB * D;
    constexpr int NCH  = MUL / KC;
    constexpr int KSh  = KC + 8;               // W (and RM-x) row stride, halves
    constexpr int NS   = NCOL + 8;             // x [k][n] stride, halves
    constexpr bool RM  = (D == 1);
    constexpr int TMW  = MCTA / WM;
    constexpr int TNW  = NCOL / WN;
    constexpr int MF   = TMW / 16;
    constexpr int NF   = TNW / 8;
    static_assert(TMW % 16 == 0 && TNW % 8 == 0 && WM * WN * 32 == NT, "tiling");
    static_assert(KC % 16 == 0 && NCH >= 2, "kc");

    constexpr int SWB   = 2 * MCTA * KSh * 2;  // W bytes per stage (hi+lo)
    constexpr int XW    = RM ? NB * KSh : KC * NS;   // halves per x array
    constexpr int SMB   = csmb(D, MCTA, NB, KC);
    static_assert(SMB <= 48 * 1024, "smem");
    constexpr int WSEG  = 2 * MCTA * (KC / 8); // W 16B segs per stage
    constexpr int CNT2  = NB * KC * D / (2 * NT);    // float2 per thread per chunk
    static_assert((NB * KC * D) % (2 * NT) == 0, "x loader");
    constexpr int SN    = NCOL + 2;
    static_assert(RM || (NB * MCTA * D) % (4 * NT) == 0, "epilogue");

    extern __shared__ __align__(16) char buf[];
    const uint32_t bu = (uint32_t)__cvta_generic_to_shared(buf);
    const uint32_t xh_u = bu + 2 * SWB;              // x hi array
    const uint32_t xl_u = xh_u + XW * 2;             // x lo array

    const int tid = threadIdx.x;
    const int v0  = blockIdx.x * MCTA;
    const int b0  = blockIdx.y * NB;
    const int wid = tid >> 5, lane = tid & 31;
    const int g = lane >> 2, tg = lane & 3;
    const int wm = wid % WM, wn = wid / WM;
    const int mb0 = wm * TMW, nb0 = wn * TNW;

    const int m_add = (lane & 7) + 8 * ((lane >> 3) & 1);   // ldsm4 row
    const int k_add = 8 * (lane >> 4);
    const int l15 = lane & 15;
    const int bn_l = l15 & 7, bk_l = 8 * (l15 >> 3);        // RM [n][k]
    const int bt_l = (l15 & 7) + 8 * (l15 >> 3);            // trans [k][n]

    float acc[MF][NF][4];
    #pragma unroll
    for (int mf = 0; mf < MF; ++mf)
        #pragma unroll
        for (int nf = 0; nf < NF; ++nf)
            #pragma unroll
            for (int q = 0; q < 4; ++q) acc[mf][nf][q] = 0.f;

    auto load_w = [&](int s, int ch) {
        const int u0 = ch * KC;
        const uint32_t wdst = bu + s * SWB;
        constexpr int WIT = (WSEG + NT - 1) / NT;
        #pragma unroll
        for (int t = 0; t < WIT; ++t) {
            int sid = tid + t * NT;
            if (WSEG % NT == 0 || sid < WSEG) {
                int arr = sid / (WSEG / 2), r = sid % (WSEG / 2);
                int m = r / (KC / 8), sg = r % (KC / 8);
                const __nv_bfloat16* gp = (arr ? g_wl : g_wh)
                    + WO + (size_t)(v0 + m) * MUL + u0 + sg * 8;
                cp16(wdst + (uint32_t)(arr * MCTA * KSh + m * KSh + sg * 8) * 2u, gp);
            }
        }
        asm volatile("cp.async.commit_group;");
    };

    auto ldg_x = [&](int ch, float2* xr) {
        const int base = XO + ch * KC * D;
        #pragma unroll
        for (int t = 0; t < CNT2; ++t) {
            int f = 2 * (tid + t * NT);
            int bl = f / (KC * D), r = f % (KC * D);
            xr[t] = *(const float2*)(x + (size_t)(b0 + bl) * FEAT + base + r);
        }
    };

    auto sts_x = [&](const float2* xr) {
        #pragma unroll
        for (int t = 0; t < CNT2; ++t) {
            int f = 2 * (tid + t * NT);
            int bl = f / (KC * D), r = f % (KC * D);
            unsigned wh, wl;
            split2(xr[t].x, xr[t].y, wh, wl);
            if (RM) {
                // [n][KSh], two adjacent k halves -> one 4B word (f even)
                uint32_t a = (uint32_t)(bl * KSh + r);       // half index, even
                *(unsigned*)((char*)buf + 2 * SWB + a * 2) = wh;
                *(unsigned*)((char*)buf + 2 * SWB + (XW + a) * 2) = wl;
            } else {
                int u0c = r / D, i0 = r % D;
                int u1c = (r + 1) / D, i1 = (r + 1) % D;
                uint32_t a0 = (uint32_t)(u0c * NS + bl * D + i0);
                uint32_t a1 = (uint32_t)(u1c * NS + bl * D + i1);
                unsigned short* H = (unsigned short*)((char*)buf + 2 * SWB);
                unsigned short* L = H + XW;
                H[a0] = (unsigned short)(wh & 0xffffu);
                H[a1] = (unsigned short)(wh >> 16);
                L[a0] = (unsigned short)(wl & 0xffffu);
                L[a1] = (unsigned short)(wl >> 16);
            }
        }
    };

    float2 xr[CNT2];
    load_w(0, 0);
    ldg_x(0, xr);

    for (int ch = 0; ch < NCH; ++ch) {
        const int s = ch & 1;
        __syncthreads();                        // prev compute done; stages free
        if (ch + 1 < NCH) load_w((ch + 1) & 1, ch + 1);
        sts_x(xr);
        if (ch + 1 < NCH) ldg_x(ch + 1, xr);
        if (ch + 1 < NCH) asm volatile("cp.async.wait_group 1;" ::: "memory");
        else              asm volatile("cp.async.wait_group 0;" ::: "memory");
        __syncthreads();

        const uint32_t whu = bu + s * SWB;
        const uint32_t wlu = whu + (uint32_t)MCTA * KSh * 2u;

        #pragma unroll
        for (int k16 = 0; k16 < KC / 16; ++k16) {
            const int kk = k16 * 16;
            unsigned ah[MF][4], al[MF][4];
            #pragma unroll
            for (int mf = 0; mf < MF; ++mf) {
                uint32_t off = (uint32_t)((mb0 + mf * 16 + m_add) * KSh
                                          + kk + k_add) * 2u;
                ldsm4(ah[mf], whu + off);
                ldsm4(al[mf], wlu + off);
            }
            #pragma unroll
            for (int nf = 0; nf < NF; ++nf) {
                unsigned bh[2], bl2[2];
                if (RM) {
                    uint32_t off = (uint32_t)((nb0 + nf * 8 + bn_l) * KSh
                                              + kk + bk_l) * 2u;
                    ldsm2(bh, xh_u + off);
                    ldsm2(bl2, xl_u + off);
                } else {
                    uint32_t off = (uint32_t)((kk + bt_l) * NS
                                              + nb0 + nf * 8) * 2u;
                    ldsm2t(bh, xh_u + off);
                    ldsm2t(bl2, xl_u + off);
                }
                #pragma unroll
                for (int mf = 0; mf < MF; ++mf) {
                    mma16(acc[mf][nf], ah[mf], bh);
                    mma16(acc[mf][nf], al[mf], bh);
                    mma16(acc[mf][nf], ah[mf], bl2);
                }
            }
        }
    }

    if (RM) {
        // D=1: direct fragment stores; m (=v) is y's fast axis
        #pragma unroll
        for (int mf = 0; mf < MF; ++mf)
            #pragma unroll
            for (int nf = 0; nf < NF; ++nf) {
                int m = v0 + mb0 + mf * 16 + g;
                int n = b0 + nb0 + nf * 8 + 2 * tg;
                y[(size_t)n * FEAT + XO + m]           = acc[mf][nf][0];
                y[(size_t)(n + 1) * FEAT + XO + m]     = acc[mf][nf][1];
                y[(size_t)n * FEAT + XO + m + 8]       = acc[mf][nf][2];
                y[(size_t)(n + 1) * FEAT + XO + m + 8] = acc[mf][nf][3];
            }
    } else {
        // D>1: stage via smem, write coalesced float4
        __syncthreads();
        float* S = (float*)buf;
        #pragma unroll
        for (int mf = 0; mf < MF; ++mf)
            #pragma unroll
            for (int nf = 0; nf < NF; ++nf) {
                int mb = mb0 + mf * 16, nn = nb0 + nf * 8 + 2 * tg;
                S[(mb + g) * SN + nn]         = acc[mf][nf][0];
                S[(mb + g) * SN + nn + 1]     = acc[mf][nf][1];
                S[(mb + g + 8) * SN + nn]     = acc[mf][nf][2];
                S[(mb + g + 8) * SN + nn + 1] = acc[mf][nf][3];
            }
        __syncthreads();

        constexpr int ROW = MCTA * D;
        #pragma unroll
        for (int t = 0; t < NB * ROW / 4 / NT; ++t) {
            int f4 = (tid + t * NT) * 4;
            int bl = f4 / ROW, r = f4 % ROW;
            float4 o;
            o.x = S[((r + 0) / D) * SN + bl * D + (r + 0) % D];
            o.y = S[((r + 1) / D) * SN + bl * D + (r + 1) % D];
            o.z = S[((r + 2) / D) * SN + bl * D + (r + 2) % D];
            o.w = S[((r + 3) / D) * SN + bl * D + (r + 3) % D];
            *(float4*)(y + (size_t)(b0 + bl) * FEAT + XO + v0 * D + r) = o;
        }
    }
}

extern "C" void kernel_launch(void* const* d_in, const int* in_sizes, int n_in,
                              void* d_out, int out_size) {
    const float* x = (const float*)d_in[0];
    const float* w = (const float*)d_in[1];
    float* y = (float*)d_out;
    (void)in_sizes; (void)n_in; (void)out_size;

    wsplit_kernel<<<(W_DIM + NT - 1) / NT, NT>>>(w);

    //       MUL  D   XO    WO   MCTA NB  KC WM WN MINB   grid(v-tiles, batch-tiles)
    eqlin3<256, 1,   0,     0,  64, 64, 32, 2, 4, 3>
        <<<dim3(4, BATCH_N / 64), NT, csmb(1, 64, 64, 32)>>>(x, y);
    eqlin3<128, 3, 256, 65536,  64, 32, 32, 2, 4, 3>
        <<<dim3(2, BATCH_N / 32), NT, csmb(3, 64, 32, 32)>>>(x, y);
    eqlin3< 64, 5, 640, 81920,  64, 16, 32, 4, 2, 3>
        <<<dim3(1, BATCH_N / 16), NT, csmb(5, 64, 16, 32)>>>(x, y);
    eqlin3< 32, 7, 960, 86016,  32, 32, 16, 2, 4, 3>
        <<<dim3(1, BATCH_N / 32), NT, csmb(7, 32, 32, 16)>>>(x, y);
}

// round 11
// speedup vs baseline: 1.1281x; 1.1281x over previous
#include <cuda_runtime.h>
#include <cuda_bf16.h>
#include <stdint.h>

// Equivariant linear via block-diagonal GEMMs, bf16 3-term emulation on
// m16n8k16 tensor cores.
//  - W: pre-split bf16 (hi,lo) globals -> smem via cp.async, 2-stage pipeline.
//  - x, D=1 : LDG f32 -> regs (chunk ahead), split hi/lo once -> bf16 smem
//             [n][k]; B fragments via paired ldmatrix.x4.
//  - x, D>1 : raw f32 rows via cp.async 2-stage; hi/lo split in registers at
//             B-fragment build (proven R8 path).
// acc += wh*xh + wl*xh + wh*xl   (dropped wl*xl ~ 2^-18).
// Blocks (mul, d, x_off, w_off):
//   (256,1,0,0) (128,3,256,65536) (64,5,640,81920) (32,7,960,86016)

#define FEAT 1184
#define BATCH_N 131072
#define NT 256
#define W_DIM 87040

__device__ __nv_bfloat16 g_wh[W_DIM];
__device__ __nv_bfloat16 g_wl[W_DIM];

__device__ __forceinline__ void cp16(uint32_t saddr, const void* gaddr) {
    asm volatile("cp.async.ca.shared.global [%0], [%1], 16;" :: "r"(saddr), "l"(gaddr));
}
__device__ __forceinline__ void ldsm4(unsigned* r, uint32_t a) {
    asm volatile("ldmatrix.sync.aligned.m8n8.x4.shared.b16 {%0,%1,%2,%3}, [%4];"
        : "=r"(r[0]), "=r"(r[1]), "=r"(r[2]), "=r"(r[3]) : "r"(a));
}
__device__ __forceinline__ void mma16(float* d, const unsigned* a, const unsigned* b) {
    asm volatile("mma.sync.aligned.m16n8k16.row.col.f32.bf16.bf16.f32 "
        "{%0,%1,%2,%3}, {%4,%5,%6,%7}, {%8,%9}, {%0,%1,%2,%3};"
        : "+f"(d[0]), "+f"(d[1]), "+f"(d[2]), "+f"(d[3])
        : "r"(a[0]), "r"(a[1]), "r"(a[2]), "r"(a[3]), "r"(b[0]), "r"(b[1]));
}
__device__ __forceinline__ unsigned cvt2(float vh, float vl) {
    unsigned r;
    asm("cvt.rn.bf16x2.f32 %0, %1, %2;" : "=r"(r) : "f"(vh), "f"(vl));
    return r;
}
// two floats -> packed hi word {v1,v0} and residual word
__device__ __forceinline__ void split2(float v0, float v1, unsigned &wh, unsigned &wl) {
    wh = cvt2(v1, v0);
    float h0 = __uint_as_float(wh << 16);
    float h1 = __uint_as_float(wh & 0xffff0000u);
    wl = cvt2(v1 - h1, v0 - h0);
}
// v0..v3 at ascending k (k,k+1,k+8,k+9); hi frag + residual frag
__device__ __forceinline__ void split4(float v0, float v1, float v2, float v3,
                                       unsigned* bh, unsigned* bl) {
    split2(v0, v1, bh[0], bl[0]);
    split2(v2, v3, bh[1], bl[1]);
}

__global__ void wsplit_kernel(const float* __restrict__ w) {
    int idx = blockIdx.x * NT + threadIdx.x;
    if (idx >= W_DIM) return;
    float c = (idx < 65536) ? 0.0625f
            : (idx < 81920) ? 0.08838834764831845f
            : (idx < 86016) ? 0.125f
                            : 0.17677669529663687f;
    float v = w[idx] * c;
    __nv_bfloat16 h = __float2bfloat16_rn(v);
    g_wh[idx] = h;
    g_wl[idx] = __float2bfloat16_rn(v - __bfloat162float(h));
}

__host__ __device__ constexpr int cmax(int a, int b) { return a > b ? a : b; }
__host__ __device__ constexpr int csmb(int D, int MCTA, int NB, int KC) {
    int KSh = KC + 8;
    int SWB = 2 * MCTA * KSh * 2;
    if (D == 1) return 2 * SWB + 2 * (NB * KSh) * 2;
    int SXB = NB * (KC * D + 4) * 4;
    int mainb = 2 * SWB + 2 * SXB;
    int epib = MCTA * (NB * D + 2) * 4;
    return cmax(mainb, epib);
}

template<int MUL, int D, int XO, int WO, int MCTA, int NB, int KC, int WM, int WN,
         int MINB>
__global__ __launch_bounds__(NT, MINB)
void eqlin4(const float* __restrict__ x, float* __restrict__ y)
{
    constexpr int NCOL = NB * D;
    constexpr int NCH  = MUL / KC;
    constexpr int KSh  = KC + 8;               // W (and RM-x) row stride, halves
    constexpr int XRS  = KC * D + 4;           // D>1 x f32 row stride
    constexpr bool RM  = (D == 1);
    constexpr int TMW  = MCTA / WM;
    constexpr int TNW  = NCOL / WN;
    constexpr int MF   = TMW / 16;
    constexpr int NF   = TNW / 8;
    static_assert(TMW % 16 == 0 && TNW % 8 == 0 && WM * WN * 32 == NT, "tiling");
    static_assert(KC % 16 == 0 && NCH >= 2, "kc");
    static_assert(!RM || NF % 2 == 0, "rm pairs");

    constexpr int SWB  = 2 * MCTA * KSh * 2;   // W bytes per stage (hi+lo)
    constexpr int XW   = NB * KSh;             // RM halves per x array
    constexpr int SXB  = NB * XRS * 4;         // D>1 x bytes per stage
    constexpr int SMB  = csmb(D, MCTA, NB, KC);
    static_assert(SMB <= 48 * 1024, "smem");
    constexpr int WSEG = 2 * MCTA * (KC / 8);  // W 16B segs per stage
    constexpr int XSEG = NB * KC * D / 4;      // D>1 x 16B segs per stage
    constexpr int CNT2 = RM ? NB * KC / (2 * NT) : 1;  // RM float2/thread/chunk
    static_assert(!RM || (NB * KC) % (2 * NT) == 0, "rm loader");
    constexpr int SN   = NCOL + 2;
    static_assert(RM || (NB * MCTA * D) % (4 * NT) == 0, "epilogue");

    extern __shared__ __align__(16) char buf[];
    const uint32_t bu = (uint32_t)__cvta_generic_to_shared(buf);
    const uint32_t xh_u = bu + 2 * SWB;        // RM: x hi array
    const uint32_t xl_u = xh_u + XW * 2;       // RM: x lo array

    const int tid = threadIdx.x;
    const int v0  = blockIdx.x * MCTA;
    const int b0  = blockIdx.y * NB;
    const int wid = tid >> 5, lane = tid & 31;
    const int g = lane >> 2, tg = lane & 3;
    const int wm = wid % WM, wn = wid / WM;
    const int mb0 = wm * TMW, nb0 = wn * TNW;

    const int m_add = (lane & 7) + 8 * ((lane >> 3) & 1);   // A ldsm4 row
    const int k_add = 8 * (lane >> 4);                      // A ldsm4 col
    const int bq  = ((lane >> 4) << 3) + (lane & 7);        // B ldsm4 row (RM)
    const int bqc = ((lane >> 3) & 1) << 3;                 // B ldsm4 col (RM)

    int xoff[NF];                                           // D>1 x word offsets
    #pragma unroll
    for (int nf = 0; nf < NF; ++nf) {
        int n = nb0 + nf * 8 + g;
        xoff[nf] = RM ? 0 : (n / D) * XRS + (n % D);
    }

    float acc[MF][NF][4];
    #pragma unroll
    for (int mf = 0; mf < MF; ++mf)
        #pragma unroll
        for (int nf = 0; nf < NF; ++nf)
            #pragma unroll
            for (int q = 0; q < 4; ++q) acc[mf][nf][q] = 0.f;

    auto load_w = [&](int s, int ch) {
        const int u0 = ch * KC;
        const uint32_t wdst = bu + s * SWB;
        constexpr int WIT = (WSEG + NT - 1) / NT;
        #pragma unroll
        for (int t = 0; t < WIT; ++t) {
            int sid = tid + t * NT;
            if (WSEG % NT == 0 || sid < WSEG) {
                int arr = sid / (WSEG / 2), r = sid % (WSEG / 2);
                int m = r / (KC / 8), sg = r % (KC / 8);
                const __nv_bfloat16* gp = (arr ? g_wl : g_wh)
                    + WO + (size_t)(v0 + m) * MUL + u0 + sg * 8;
                cp16(wdst + (uint32_t)(arr * MCTA * KSh + m * KSh + sg * 8) * 2u, gp);
            }
        }
    };

    // ---- compute one chunk (stage s), W from stage, x per-mode
    auto compute = [&](int s, const float* xp) {
        const uint32_t whu = bu + s * SWB;
        const uint32_t wlu = whu + (uint32_t)MCTA * KSh * 2u;
        #pragma unroll
        for (int k16 = 0; k16 < KC / 16; ++k16) {
            const int kk = k16 * 16;
            unsigned ah[MF][4], al[MF][4];
            #pragma unroll
            for (int mf = 0; mf < MF; ++mf) {
                uint32_t off = (uint32_t)((mb0 + mf * 16 + m_add) * KSh
                                          + kk + k_add) * 2u;
                ldsm4(ah[mf], whu + off);
                ldsm4(al[mf], wlu + off);
            }
            unsigned bh[NF][2], bl2[NF][2];
            if (RM) {
                #pragma unroll
                for (int p = 0; p < NF / 2; ++p) {
                    uint32_t off = (uint32_t)((nb0 + p * 16 + bq) * KSh
                                              + kk + bqc) * 2u;
                    unsigned t4[4];
                    ldsm4(t4, xh_u + off);
                    bh[2*p][0] = t4[0]; bh[2*p][1] = t4[1];
                    bh[2*p+1][0] = t4[2]; bh[2*p+1][1] = t4[3];
                    ldsm4(t4, xl_u + off);
                    bl2[2*p][0] = t4[0]; bl2[2*p][1] = t4[1];
                    bl2[2*p+1][0] = t4[2]; bl2[2*p+1][1] = t4[3];
                }
            } else {
                #pragma unroll
                for (int nf = 0; nf < NF; ++nf) {
                    const float* p = xp + xoff[nf] + (kk + 2 * tg) * D;
                    split4(p[0], p[D], p[8 * D], p[9 * D], bh[nf], bl2[nf]);
                }
            }
            #pragma unroll
            for (int mf = 0; mf < MF; ++mf)
                #pragma unroll
                for (int nf = 0; nf < NF; ++nf) {
                    mma16(acc[mf][nf], ah[mf], bh[nf]);
                    mma16(acc[mf][nf], al[mf], bh[nf]);
                    mma16(acc[mf][nf], ah[mf], bl2[nf]);
                }
        }
    };

    if (RM) {
        // ---- D=1 pipeline: W cp.async 2-stage; x LDG->reg->split->bf16 smem
        float2 xr[CNT2];
        auto ldg_x = [&](int ch, float2* r) {
            const int base = XO + ch * KC;
            #pragma unroll
            for (int t = 0; t < CNT2; ++t) {
                int f = 2 * (tid + t * NT);
                int bl = f / KC, rr = f % KC;
                r[t] = *(const float2*)(x + (size_t)(b0 + bl) * FEAT + base + rr);
            }
        };
        auto sts_x = [&](const float2* r) {
            #pragma unroll
            for (int t = 0; t < CNT2; ++t) {
                int f = 2 * (tid + t * NT);
                int bl = f / KC, rr = f % KC;
                unsigned wh, wl;
                split2(r[t].x, r[t].y, wh, wl);
                uint32_t a = (uint32_t)(bl * KSh + rr) * 2u;
                *(unsigned*)((char*)buf + (xh_u - bu) + a) = wh;
                *(unsigned*)((char*)buf + (xl_u - bu) + a) = wl;
            }
        };

        load_w(0, 0);
        asm volatile("cp.async.commit_group;");
        ldg_x(0, xr);

        for (int ch = 0; ch < NCH; ++ch) {
            const int s = ch & 1;
            __syncthreads();
            if (ch + 1 < NCH) {
                load_w(s ^ 1, ch + 1);
                asm volatile("cp.async.commit_group;");
            }
            sts_x(xr);
            if (ch + 1 < NCH) ldg_x(ch + 1, xr);
            if (ch + 1 < NCH) asm volatile("cp.async.wait_group 1;" ::: "memory");
            else              asm volatile("cp.async.wait_group 0;" ::: "memory");
            __syncthreads();
            compute(s, nullptr);
        }

        // direct fragment stores; m (=v) is y's fast axis
        #pragma unroll
        for (int mf = 0; mf < MF; ++mf)
            #pragma unroll
            for (int nf = 0; nf < NF; ++nf) {
                int m = v0 + mb0 + mf * 16 + g;
                int n = b0 + nb0 + nf * 8 + 2 * tg;
                y[(size_t)n * FEAT + XO + m]           = acc[mf][nf][0];
                y[(size_t)(n + 1) * FEAT + XO + m]     = acc[mf][nf][1];
                y[(size_t)n * FEAT + XO + m + 8]       = acc[mf][nf][2];
                y[(size_t)(n + 1) * FEAT + XO + m + 8] = acc[mf][nf][3];
            }
    } else {
        // ---- D>1 pipeline: W + raw f32 x, both cp.async 2-stage
        auto load_x = [&](int s, int ch) {
            const uint32_t xdst = bu + 2 * SWB + s * SXB;
            const int base = XO + ch * KC * D;
            constexpr int XIT = (XSEG + NT - 1) / NT;
            #pragma unroll
            for (int t = 0; t < XIT; ++t) {
                int sid = tid + t * NT;
                if (XSEG % NT == 0 || sid < XSEG) {
                    int bl = sid / (KC * D / 4), sg = sid % (KC * D / 4);
                    const float* gp = x + (size_t)(b0 + bl) * FEAT + base + sg * 4;
                    cp16(xdst + (uint32_t)(bl * XRS + sg * 4) * 4u, gp);
                }
            }
        };

        load_w(0, 0); load_x(0, 0);
        asm volatile("cp.async.commit_group;");

        for (int ch = 0; ch < NCH; ++ch) {
            const int s = ch & 1;
            if (ch + 1 < NCH) {
                load_w(s ^ 1, ch + 1); load_x(s ^ 1, ch + 1);
                asm volatile("cp.async.commit_group;");
                asm volatile("cp.async.wait_group 1;" ::: "memory");
            } else {
                asm volatile("cp.async.wait_group 0;" ::: "memory");
            }
            __syncthreads();
            compute(s, (const float*)(buf + 2 * SWB + s * SXB));
            __syncthreads();
        }

        // stage via smem, write coalesced float4
        float* S = (float*)buf;
        #pragma unroll
        for (int mf = 0; mf < MF; ++mf)
            #pragma unroll
            for (int nf = 0; nf < NF; ++nf) {
                int mb = mb0 + mf * 16, nn = nb0 + nf * 8 + 2 * tg;
                S[(mb + g) * SN + nn]         = acc[mf][nf][0];
                S[(mb + g) * SN + nn + 1]     = acc[mf][nf][1];
                S[(mb + g + 8) * SN + nn]     = acc[mf][nf][2];
                S[(mb + g + 8) * SN + nn + 1] = acc[mf][nf][3];
            }
        __syncthreads();

        constexpr int ROW = MCTA * D;
        #pragma unroll
        for (int t = 0; t < NB * ROW / 4 / NT; ++t) {
            int f4 = (tid + t * NT) * 4;
            int bl = f4 / ROW, r = f4 % ROW;
            float4 o;
            o.x = S[((r + 0) / D) * SN + bl * D + (r + 0) % D];
            o.y = S[((r + 1) / D) * SN + bl * D + (r + 1) % D];
            o.z = S[((r + 2) / D) * SN + bl * D + (r + 2) % D];
            o.w = S[((r + 3) / D) * SN + bl * D + (r + 3) % D];
            *(float4*)(y + (size_t)(b0 + bl) * FEAT + XO + v0 * D + r) = o;
        }
    }
}

extern "C" void kernel_launch(void* const* d_in, const int* in_sizes, int n_in,
                              void* d_out, int out_size) {
    const float* x = (const float*)d_in[0];
    const float* w = (const float*)d_in[1];
    float* y = (float*)d_out;
    (void)in_sizes; (void)n_in; (void)out_size;

    wsplit_kernel<<<(W_DIM + NT - 1) / NT, NT>>>(w);

    //       MUL  D   XO    WO   MCTA  NB  KC WM WN MINB   grid(v, b)
    eqlin4<256, 1,   0,     0,  64, 128, 32, 2, 4, 2>
        <<<dim3(4, BATCH_N / 128), NT, csmb(1, 64, 128, 32)>>>(x, y);
    eqlin4<128, 3, 256, 65536,  64,  32, 32, 2, 4, 2>
        <<<dim3(2, BATCH_N / 32), NT, csmb(3, 64, 32, 32)>>>(x, y);
    eqlin4< 64, 5, 640, 81920,  64,  32, 16, 2, 4, 2>
        <<<dim3(1, BATCH_N / 32), NT, csmb(5, 64, 32, 16)>>>(x, y);
    eqlin4< 32, 7, 960, 86016,  32,  32, 16, 2, 4, 3>
        <<<dim3(1, BATCH_N / 32), NT, csmb(7, 32, 32, 16)>>>(x, y);
}